// round 11
// baseline (speedup 1.0000x reference)
#include <cuda_runtime.h>
#include <cuda_bf16.h>
#include <math.h>

#define NODES 50000
#define DF 64
#define HF 64
#define BN_EPS 1e-3f
#define ROWP 68
#define ROWP2 132

typedef unsigned long long ull;

// ---------------- device scratch (static, no allocs) ----------------
__device__ float g_Wm1[DF * HF];
__device__ float g_cm1[HF];
__device__ float g_Wm2[HF * HF];
__device__ float g_cm2[HF];
__device__ float g_Wu1[(DF + HF) * HF];
__device__ float g_cu1[HF];
__device__ float g_Wu2[HF * HF];
__device__ float g_cu2[HF];
__device__ float g_agg[(size_t)NODES * HF];   // segment sums
__device__ float g_cnt[NODES];                // segment counts
__device__ float g_msg[(size_t)NODES * HF];   // per-node precomputed message
// packed tf32 hi/lo weights: P[kt*256 + n*4 + r] =
//   (hi W[8kt+r][n], hi W[8kt+r+4][n], lo W[8kt+r][n], lo W[8kt+r+4][n])
__device__ float4 g_We1p[2048];
__device__ float4 g_We2p[2048];
__device__ float4 g_Wm1p[2048];
__device__ float4 g_Wm2p[2048];
__device__ float4 g_Wu1p[4096];   // K=128
__device__ float4 g_Wu2p[2048];

// ---------------- helpers ----------------
__device__ __forceinline__ float gelu_f(float v) {
    return 0.5f * v * (1.0f + erff(v * 0.70710678118654752440f));
}
__device__ __forceinline__ void red_add_v4(float* p, float a, float b, float c, float d) {
    asm volatile("red.global.add.v4.f32 [%0], {%1, %2, %3, %4};"
                 :: "l"(p), "f"(a), "f"(b), "f"(c), "f"(d) : "memory");
}
__device__ __forceinline__ void red_add_f(float* p, float a) {
    asm volatile("red.global.add.f32 [%0], %1;" :: "l"(p), "f"(a) : "memory");
}
__device__ __forceinline__ void cp_async16(unsigned saddr, const void* gptr) {
    asm volatile("cp.async.cg.shared.global [%0], [%1], 16;" :: "r"(saddr), "l"(gptr));
}
__device__ __forceinline__ unsigned tf32r(float v) {
    unsigned r;
    asm("cvt.rna.tf32.f32 %0, %1;" : "=r"(r) : "f"(v));
    return r;
}
__device__ __forceinline__ ull packf2(float a, float b) {
    ull r;
    asm("mov.b64 %0, {%1, %2};" : "=l"(r) : "f"(a), "f"(b));
    return r;
}
__device__ __forceinline__ float2 unpackf2(ull v) {
    float2 f;
    asm("mov.b64 {%0, %1}, %2;" : "=f"(f.x), "=f"(f.y) : "l"(v));
    return f;
}
__device__ __forceinline__ void mma8(float c[4],
                                     unsigned a0, unsigned a1, unsigned a2, unsigned a3,
                                     unsigned b0, unsigned b1) {
    asm volatile("mma.sync.aligned.m16n8k8.row.col.f32.tf32.tf32.f32 "
                 "{%0,%1,%2,%3}, {%4,%5,%6,%7}, {%8,%9}, {%0,%1,%2,%3};"
                 : "+f"(c[0]), "+f"(c[1]), "+f"(c[2]), "+f"(c[3])
                 : "r"(a0), "r"(a1), "r"(a2), "r"(a3), "r"(b0), "r"(b1));
}

// =====================================================================
// Warp GEMM: 16 rows x 64 cols, K = KT*8, A in smem (row stride RP),
// W packed float4 hi/lo in smem, 2-pass tf32 (A-hi only; W = hi + lo).
// =====================================================================
template <int KT, int RP>
__device__ __forceinline__ void wgemm16(const float* __restrict__ As,
                                        const float4* __restrict__ Wp,
                                        const float* __restrict__ bias,
                                        int lr, int lc, float acc[8][4])
{
#pragma unroll
    for (int nt = 0; nt < 8; nt++) {
        float b0 = bias[nt * 8 + 2 * lc];
        float b1 = bias[nt * 8 + 2 * lc + 1];
        acc[nt][0] = b0; acc[nt][1] = b1; acc[nt][2] = b0; acc[nt][3] = b1;
    }
#pragma unroll
    for (int kt = 0; kt < KT; kt++) {
        float a0 = As[lr * RP + kt * 8 + lc];
        float a1 = As[(lr + 8) * RP + kt * 8 + lc];
        float a2 = As[lr * RP + kt * 8 + lc + 4];
        float a3 = As[(lr + 8) * RP + kt * 8 + lc + 4];
        unsigned h0 = tf32r(a0), h1 = tf32r(a1), h2 = tf32r(a2), h3 = tf32r(a3);
        const float4* wb = Wp + kt * 256 + lr * 4 + lc;
#pragma unroll
        for (int nt = 0; nt < 8; nt++) {
            float4 bq = wb[nt * 32];
            mma8(acc[nt], h0, h1, h2, h3,
                 __float_as_uint(bq.x), __float_as_uint(bq.y));
            mma8(acc[nt], h0, h1, h2, h3,
                 __float_as_uint(bq.z), __float_as_uint(bq.w));
        }
    }
}

// ---------------- fold kernel: BN -> weights ----------------
__global__ void fold_kernel(
    const float* __restrict__ m_g1, const float* __restrict__ m_b1,
    const float* __restrict__ m_mu1, const float* __restrict__ m_v1,
    const float* __restrict__ m_W1, const float* __restrict__ m_c1,
    const float* __restrict__ m_g2, const float* __restrict__ m_b2,
    const float* __restrict__ m_mu2, const float* __restrict__ m_v2,
    const float* __restrict__ m_W2, const float* __restrict__ m_c2,
    const float* __restrict__ u_g1, const float* __restrict__ u_b1,
    const float* __restrict__ u_mu1, const float* __restrict__ u_v1,
    const float* __restrict__ u_W1, const float* __restrict__ u_c1,
    const float* __restrict__ u_g2, const float* __restrict__ u_b2,
    const float* __restrict__ u_mu2, const float* __restrict__ u_v2,
    const float* __restrict__ u_W2, const float* __restrict__ u_c2)
{
    int t = blockIdx.x * blockDim.x + threadIdx.x;
    if (t < 4096) {
        int k = t >> 6;
        float s = m_g1[k] * rsqrtf(m_v1[k] + BN_EPS);
        g_Wm1[t] = s * m_W1[t];
    } else if (t < 8192) {
        int i = t - 4096; int k = i >> 6;
        float s = m_g2[k] * rsqrtf(m_v2[k] + BN_EPS);
        g_Wm2[i] = s * m_W2[i];
    } else if (t < 16384) {
        int i = t - 8192; int k = i >> 6;
        float s = u_g1[k] * rsqrtf(u_v1[k] + BN_EPS);
        g_Wu1[i] = s * u_W1[i];
    } else if (t < 20480) {
        int i = t - 16384; int k = i >> 6;
        float s = u_g2[k] * rsqrtf(u_v2[k] + BN_EPS);
        g_Wu2[i] = s * u_W2[i];
    } else if (t < 20544) {
        int j = t - 20480;
        float sum = m_c1[j];
        for (int k = 0; k < DF; k++) {
            float s = m_g1[k] * rsqrtf(m_v1[k] + BN_EPS);
            sum += (m_b1[k] - m_mu1[k] * s) * m_W1[k * HF + j];
        }
        g_cm1[j] = sum;
    } else if (t < 20608) {
        int j = t - 20544;
        float sum = m_c2[j];
        for (int k = 0; k < HF; k++) {
            float s = m_g2[k] * rsqrtf(m_v2[k] + BN_EPS);
            sum += (m_b2[k] - m_mu2[k] * s) * m_W2[k * HF + j];
        }
        g_cm2[j] = sum;
    } else if (t < 20672) {
        int j = t - 20608;
        float sum = u_c1[j];
        for (int k = 0; k < DF + HF; k++) {
            float s = u_g1[k] * rsqrtf(u_v1[k] + BN_EPS);
            sum += (u_b1[k] - u_mu1[k] * s) * u_W1[k * HF + j];
        }
        g_cu1[j] = sum;
    } else if (t < 20736) {
        int j = t - 20672;
        float sum = u_c2[j];
        for (int k = 0; k < HF; k++) {
            float s = u_g2[k] * rsqrtf(u_v2[k] + BN_EPS);
            sum += (u_b2[k] - u_mu2[k] * s) * u_W2[k * HF + j];
        }
        g_cu2[j] = sum;
    }
}

// ---------------- pack kernel: tf32 hi/lo split of all 6 matrices ----------------
__global__ void pack_kernel(const float* __restrict__ We1, const float* __restrict__ We2) {
    int t = blockIdx.x * blockDim.x + threadIdx.x;
    const float* W; float4* P; int i;
    if (t < 2048)       { W = g_Wm1; P = g_Wm1p; i = t; }
    else if (t < 4096)  { W = g_Wm2; P = g_Wm2p; i = t - 2048; }
    else if (t < 6144)  { W = We1;   P = g_We1p; i = t - 4096; }
    else if (t < 8192)  { W = We2;   P = g_We2p; i = t - 6144; }
    else if (t < 10240) { W = g_Wu2; P = g_Wu2p; i = t - 8192; }
    else if (t < 14336) { W = g_Wu1; P = g_Wu1p; i = t - 10240; }
    else return;
    int kt = i >> 8, rem = i & 255, n = rem >> 2, r = rem & 3;
    float w1 = W[(kt * 8 + r) * 64 + n];
    float w2 = W[(kt * 8 + r + 4) * 64 + n];
    unsigned h1 = tf32r(w1), h2 = tf32r(w2);
    float4 o;
    o.x = __uint_as_float(h1);
    o.y = __uint_as_float(h2);
    o.z = __uint_as_float(tf32r(w1 - __uint_as_float(h1)));
    o.w = __uint_as_float(tf32r(w2 - __uint_as_float(h2)));
    P[i] = o;
}

// ---------------- zero accumulators ----------------
__global__ void zero_kernel() {
    size_t total = (size_t)NODES * HF;
    for (size_t i = blockIdx.x * (size_t)blockDim.x + threadIdx.x;
         i < total; i += (size_t)gridDim.x * blockDim.x) {
        g_agg[i] = 0.0f;
        if (i < NODES) g_cnt[i] = 0.0f;
    }
}

// =====================================================================
// msg kernel: per-node message MLP via tf32 mma
// =====================================================================
#define MS_W2 8192
#define MS_B  16384
#define MS_A  16512
#define MS_TOT (16512 + 128 * ROWP)

__global__ void __launch_bounds__(256, 2)
msg_kernel(const float* __restrict__ nf, int N)
{
    extern __shared__ float sm[];
    float* sW1 = sm;
    float* sW2 = sm + MS_W2;
    float* sb  = sm + MS_B;
    float* sA  = sm + MS_A;

    int t = threadIdx.x;
    int w = t >> 5, l = t & 31;
    int lr = l >> 2, lc = l & 3;
    unsigned sbase = (unsigned)__cvta_generic_to_shared(sm);
    int n0 = blockIdx.x << 7;
    int nvalid = min(128, N - n0);

    for (int i = t; i < 2048; i += 256) {
        int r = i >> 4, q = i & 15;
        int rr = min(r, nvalid - 1);
        cp_async16(sbase + (MS_A + r * ROWP + q * 4) * 4,
                   nf + (size_t)(n0 + rr) * 64 + q * 4);
    }
    asm volatile("cp.async.commit_group;" ::: "memory");

    for (int i = t; i < 2048; i += 256) {
        ((float4*)sW1)[i] = g_Wm1p[i];
        ((float4*)sW2)[i] = g_Wm2p[i];
    }
    if (t < 64) {
        sb[t]      = g_cm1[t];
        sb[64 + t] = g_cm2[t];
    }
    asm volatile("cp.async.wait_group 0;" ::: "memory");
    __syncthreads();

    float* As = sA + w * 16 * ROWP;
    float acc[8][4];

    wgemm16<8, ROWP>(As, (const float4*)sW1, sb, lr, lc, acc);
#pragma unroll
    for (int nt = 0; nt < 8; nt++) {
        float2 p0, p1;
        p0.x = gelu_f(acc[nt][0]); p0.y = gelu_f(acc[nt][1]);
        p1.x = gelu_f(acc[nt][2]); p1.y = gelu_f(acc[nt][3]);
        *(float2*)(As + lr * ROWP + nt * 8 + 2 * lc) = p0;
        *(float2*)(As + (lr + 8) * ROWP + nt * 8 + 2 * lc) = p1;
    }
    wgemm16<8, ROWP>(As, (const float4*)sW2, sb + 64, lr, lc, acc);
    int n1 = n0 + w * 16 + lr;
    int n2 = n1 + 8;
    bool v1 = n1 < N, v2 = n2 < N;
#pragma unroll
    for (int nt = 0; nt < 8; nt++) {
        int col = nt * 8 + 2 * lc;
        if (v1) {
            float2 o; o.x = gelu_f(acc[nt][0]); o.y = gelu_f(acc[nt][1]);
            *(float2*)(g_msg + (size_t)n1 * 64 + col) = o;
        }
        if (v2) {
            float2 o; o.x = gelu_f(acc[nt][2]); o.y = gelu_f(acc[nt][3]);
            *(float2*)(g_msg + (size_t)n2 * 64 + col) = o;
        }
    }
}

// =====================================================================
// Edge kernel: tf32 2-pass edge MLP + gate + v4-shuffled scatter
// =====================================================================
#define ESM_W2 8192
#define ESM_B  16384
#define ESM_A  16512
#define ESM_TOT (16512 + 128 * ROWP)

__global__ void __launch_bounds__(256, 2)
edge_kernel(const float* __restrict__ ef,
            const int* __restrict__ src, const int* __restrict__ dst,
            const float* __restrict__ ce1, const float* __restrict__ ce2,
            int E)
{
    extern __shared__ float sm[];
    float* sW1 = sm;
    float* sW2 = sm + ESM_W2;
    float* sb  = sm + ESM_B;
    float* sA  = sm + ESM_A;

    int t = threadIdx.x;
    int w = t >> 5, l = t & 31;
    int lr = l >> 2, lc = l & 3;
    bool lowlc = (lc & 1) == 0;
    unsigned sbase = (unsigned)__cvta_generic_to_shared(sm);
    int ntiles = (E + 127) >> 7;

    if (blockIdx.x < ntiles) {
        int e0 = blockIdx.x << 7;
        for (int i = t; i < 2048; i += 256) {
            int e = i >> 4, q = i & 15;
            int ee = min(e0 + e, E - 1);
            cp_async16(sbase + (ESM_A + e * ROWP + q * 4) * 4,
                       ef + (size_t)ee * 64 + q * 4);
        }
    }
    asm volatile("cp.async.commit_group;" ::: "memory");

    for (int i = t; i < 2048; i += 256) {
        ((float4*)sW1)[i] = g_We1p[i];
        ((float4*)sW2)[i] = g_We2p[i];
    }
    if (t < 64) {
        sb[t]      = __ldg(ce1 + t);
        sb[64 + t] = __ldg(ce2 + t);
    }

    float* As = sA + w * 16 * ROWP;

    for (int tile = blockIdx.x; tile < ntiles; tile += gridDim.x) {
        asm volatile("cp.async.wait_group 0;" ::: "memory");
        __syncthreads();
        int e0 = tile << 7;

        float acc[8][4];

        // GEMM1: er1 = gelu(ef @ We1 + c1), in place
        wgemm16<8, ROWP>(As, (const float4*)sW1, sb, lr, lc, acc);
#pragma unroll
        for (int nt = 0; nt < 8; nt++) {
            float2 p0, p1;
            p0.x = gelu_f(acc[nt][0]); p0.y = gelu_f(acc[nt][1]);
            p1.x = gelu_f(acc[nt][2]); p1.y = gelu_f(acc[nt][3]);
            *(float2*)(As + lr * ROWP + nt * 8 + 2 * lc) = p0;
            *(float2*)(As + (lr + 8) * ROWP + nt * 8 + 2 * lc) = p1;
        }

        // GEMM2: er2 = er1 @ We2 + c2
        wgemm16<8, ROWP>(As, (const float4*)sW2, sb + 64, lr, lc, acc);

        // epilogue: gelu, quad-shuffle pairs into v4 chunks, gather msg[dst],
        // red.add.v4 to agg[src]. Rows are uniform across each quad, so the
        // shfl partner (lc^1) always holds the adjacent column pair.
        int el1 = e0 + w * 16 + lr;
        int el2 = el1 + 8;
        bool v1 = el1 < E, v2 = el2 < E;
        int s1 = 0, d1 = 0, s2 = 0, d2 = 0;
        if (v1) { s1 = __ldg(src + el1); d1 = __ldg(dst + el1); }
        if (v2) { s2 = __ldg(src + el2); d2 = __ldg(dst + el2); }
#pragma unroll
        for (int nt = 0; nt < 8; nt++) {
            bool owner = (((nt & 1) == 0) == lowlc);
            int cb = nt * 8 + (lc & 2) * 2;
            {
                float g0 = gelu_f(acc[nt][0]), g1 = gelu_f(acc[nt][1]);
                ull other = __shfl_xor_sync(0xFFFFFFFFu, packf2(g0, g1), 1);
                if (owner && v1) {
                    float2 po = unpackf2(other);
                    float x0, x1, x2, x3;
                    if (lowlc) { x0 = g0; x1 = g1; x2 = po.x; x3 = po.y; }
                    else       { x0 = po.x; x1 = po.y; x2 = g0; x3 = g1; }
                    float4 m = __ldg((const float4*)(g_msg + (size_t)d1 * 64 + cb));
                    red_add_v4(g_agg + (size_t)s1 * 64 + cb,
                               m.x * x0, m.y * x1, m.z * x2, m.w * x3);
                }
            }
            {
                float g2 = gelu_f(acc[nt][2]), g3 = gelu_f(acc[nt][3]);
                ull other = __shfl_xor_sync(0xFFFFFFFFu, packf2(g2, g3), 1);
                if (owner && v2) {
                    float2 po = unpackf2(other);
                    float x0, x1, x2, x3;
                    if (lowlc) { x0 = g2; x1 = g3; x2 = po.x; x3 = po.y; }
                    else       { x0 = po.x; x1 = po.y; x2 = g2; x3 = g3; }
                    float4 m = __ldg((const float4*)(g_msg + (size_t)d2 * 64 + cb));
                    red_add_v4(g_agg + (size_t)s2 * 64 + cb,
                               m.x * x0, m.y * x1, m.z * x2, m.w * x3);
                }
            }
        }
        if (t < 128) {
            int e = e0 + t;
            if (e < E) red_add_f(&g_cnt[__ldg(src + e)], 1.0f);
        }

        __syncthreads();   // all reads of sA done before restage

        int nxt = tile + gridDim.x;
        if (nxt < ntiles) {
            int ne0 = nxt << 7;
            for (int i = t; i < 2048; i += 256) {
                int e = i >> 4, q = i & 15;
                int ee = min(ne0 + e, E - 1);
                cp_async16(sbase + (ESM_A + e * ROWP + q * 4) * 4,
                           ef + (size_t)ee * 64 + q * 4);
            }
        }
        asm volatile("cp.async.commit_group;" ::: "memory");
    }
}

// =====================================================================
// node kernel: mean + update MLP via tf32 mma
// =====================================================================
#define ND_W2  16384
#define ND_B   24576
#define ND_INV 24704
#define ND_A   24832
#define ND_TOT (24832 + 128 * ROWP2)

__global__ void __launch_bounds__(256, 1)
node_kernel(const float* __restrict__ nf, float* __restrict__ out, int N)
{
    extern __shared__ float sm[];
    float* sW1  = sm;
    float* sW2  = sm + ND_W2;
    float* sb   = sm + ND_B;
    float* sInv = sm + ND_INV;
    float* sA   = sm + ND_A;

    int t = threadIdx.x;
    int w = t >> 5, l = t & 31;
    int lr = l >> 2, lc = l & 3;
    unsigned sbase = (unsigned)__cvta_generic_to_shared(sm);
    int n0 = blockIdx.x << 7;
    int nvalid = min(128, N - n0);

    for (int i = t; i < 2048; i += 256) {
        int r = i >> 4, q = i & 15;
        int rr = min(r, nvalid - 1);
        cp_async16(sbase + (ND_A + r * ROWP2 + q * 4) * 4,
                   nf + (size_t)(n0 + rr) * 64 + q * 4);
        cp_async16(sbase + (ND_A + r * ROWP2 + 64 + q * 4) * 4,
                   g_agg + (size_t)(n0 + rr) * 64 + q * 4);
    }
    asm volatile("cp.async.commit_group;" ::: "memory");

    for (int i = t; i < 4096; i += 256) ((float4*)sW1)[i] = g_Wu1p[i];
    for (int i = t; i < 2048; i += 256) ((float4*)sW2)[i] = g_Wu2p[i];
    if (t < 64) {
        sb[t]      = g_cu1[t];
        sb[64 + t] = g_cu2[t];
    }
    if (t < 128) {
        int rr = min(t, nvalid - 1);
        sInv[t] = 1.0f / fmaxf(g_cnt[n0 + rr], 1.0f);
    }
    asm volatile("cp.async.wait_group 0;" ::: "memory");
    __syncthreads();

    for (int i = t; i < 8192; i += 256) {
        int r = i >> 6, c = i & 63;
        sA[r * ROWP2 + 64 + c] *= sInv[r];
    }
    __syncthreads();

    float* As = sA + w * 16 * ROWP2;
    float acc[8][4];

    wgemm16<16, ROWP2>(As, (const float4*)sW1, sb, lr, lc, acc);
#pragma unroll
    for (int nt = 0; nt < 8; nt++) {
        float2 p0, p1;
        p0.x = gelu_f(acc[nt][0]); p0.y = gelu_f(acc[nt][1]);
        p1.x = gelu_f(acc[nt][2]); p1.y = gelu_f(acc[nt][3]);
        *(float2*)(As + lr * ROWP2 + nt * 8 + 2 * lc) = p0;
        *(float2*)(As + (lr + 8) * ROWP2 + nt * 8 + 2 * lc) = p1;
    }
    wgemm16<8, ROWP2>(As, (const float4*)sW2, sb + 64, lr, lc, acc);
    int n1 = n0 + w * 16 + lr;
    int n2 = n1 + 8;
    bool v1 = n1 < N, v2 = n2 < N;
#pragma unroll
    for (int nt = 0; nt < 8; nt++) {
        int col = nt * 8 + 2 * lc;
        if (v1) {
            float2 o; o.x = gelu_f(acc[nt][0]); o.y = gelu_f(acc[nt][1]);
            *(float2*)(out + (size_t)n1 * 64 + col) = o;
        }
        if (v2) {
            float2 o; o.x = gelu_f(acc[nt][2]); o.y = gelu_f(acc[nt][3]);
            *(float2*)(out + (size_t)n2 * 64 + col) = o;
        }
    }
}

// ---------------- launch ----------------
extern "C" void kernel_launch(void* const* d_in, const int* in_sizes, int n_in,
                              void* d_out, int out_size)
{
    bool dictOrder = (in_sizes[2] > 64);
    const float* nf = (const float*)d_in[0];
    const float* ef = (const float*)d_in[1];
    const int* src = (const int*)d_in[dictOrder ? 2 : 30];
    const int* dst = (const int*)d_in[dictOrder ? 3 : 31];
    int p0 = dictOrder ? 4 : 2;
    const float* P[28];
    for (int i = 0; i < 28; i++) P[i] = (const float*)d_in[p0 + i];

    int E = in_sizes[1] / 64;
    int N = in_sizes[0] / 64;

    cudaFuncSetAttribute(msg_kernel, cudaFuncAttributeMaxDynamicSharedMemorySize,
                         MS_TOT * (int)sizeof(float));
    cudaFuncSetAttribute(edge_kernel, cudaFuncAttributeMaxDynamicSharedMemorySize,
                         ESM_TOT * (int)sizeof(float));
    cudaFuncSetAttribute(node_kernel, cudaFuncAttributeMaxDynamicSharedMemorySize,
                         ND_TOT * (int)sizeof(float));

    fold_kernel<<<(20736 + 255) / 256, 256>>>(
        P[0], P[1], P[2], P[3], P[4], P[5], P[6], P[7], P[8], P[9], P[10], P[11],
        P[16], P[17], P[18], P[19], P[20], P[21], P[22], P[23], P[24], P[25], P[26], P[27]);
    pack_kernel<<<56, 256>>>(P[12], P[14]);
    zero_kernel<<<2048, 256>>>();
    msg_kernel<<<(N + 127) / 128, 256, MS_TOT * sizeof(float)>>>(nf, N);
    edge_kernel<<<296, 256, ESM_TOT * sizeof(float)>>>(
        ef, src, dst, P[13], P[15], E);
    node_kernel<<<(N + 127) / 128, 256, ND_TOT * sizeof(float)>>>(
        nf, (float*)d_out, N);
}